// round 6
// baseline (speedup 1.0000x reference)
#include <cuda_runtime.h>

#define T_LEN 131072
#define W     32                 // FIR taps: rho^32 ~ 2e-7 (fp32 noise floor)
#define T_SEQ 80                 // exact sequential prefix
#define TB    128                // timesteps per FIR block
#define TPT   4                  // timesteps per thread
#define NTH   ((TB / TPT) * 6)   // 192 threads
#define N_RIC 14                 // Riccati iterations to fixed point
#define NROWS (TB + W)           // 160 shared rows (W-row halo incl. a_{t-1} taps)

__global__ __launch_bounds__(NTH)
void kf_kernel(const float* __restrict__ meas,
               const float* __restrict__ Qm,
               const float* __restrict__ Rm,
               float* __restrict__ out) {
    float* est  = out;
    float* pred = out + (size_t)T_LEN * 6;
    float* vel  = out + (size_t)2 * T_LEN * 6;

    // ---------------- block 0: exact sequential transient ----------------
    if (blockIdx.x == 0) {
        const int d = threadIdx.x;
        if (d >= 6) return;
        const float q = Qm[0];
        const float r = Rm[0];
        float m00 = 1.f, m01 = 0.f, m11 = 1.f;   // cov_init = I12 -> M0 = I2
        float m0 = meas[d], m1 = meas[6 + d];
        est [d] = m0;  est [6 + d] = m1;
        pred[d] = m0;  pred[6 + d] = m1;
        vel [d] = m1 - m0;
        float a = m1, b = m0;
        for (int t = 2; t < T_SEQ; t++) {
            float Mp00 = 4.f * (m00 - m01) + m11 + q;
            float Mp01 = 2.f * m00 - m01;
            float Mp11 = m00;
            float inv  = __fdividef(1.f, Mp00 + r);
            float k1 = Mp00 * inv, k2 = Mp01 * inv;
            m00 = Mp00 - k1 * Mp00;
            m01 = Mp01 - k1 * Mp01;
            m11 = Mp11 - k2 * Mp01;
            float p  = 2.f * a - b;
            float e  = meas[t * 6 + d] - p;
            float an = fmaf(k1, e, p);
            float bn = fmaf(k2, e, a);
            est [t * 6 + d]       = an;
            pred[t * 6 + d]       = p;
            vel [(t - 1) * 6 + d] = an - bn;
            a = an; b = bn;
        }
        pred[T_SEQ * 6 + d] = 2.f * a - b;   // row T_SEQ: only writer
        return;
    }

    // ---------------- FIR blocks ----------------
    __shared__ float sm[NROWS * 7];   // stride 7: <=2-way bank conflicts
    __shared__ float swa[W];          // a-FIR coefficients
    __shared__ float s_c;             // c = k2/(1-k1)

    const int t0   = T_SEQ + (blockIdx.x - 1) * TB;
    const int base = t0 - W;                       // >= 48

    if (threadIdx.x == 0) {
        // short coefficient bubble; warp 0 lanes 1-31 do NOT load, so this
        // chain does not serialize against any LDG/STS in its own warp
        const float q = Qm[0], r = Rm[0];
        float m00 = 1.f, m01 = 0.f, m11 = 1.f;
        float k1 = 0.f, k2 = 0.f;
        for (int it = 0; it < N_RIC; it++) {
            float Mp00 = 4.f * (m00 - m01) + m11 + q;
            float Mp01 = 2.f * m00 - m01;
            float Mp11 = m00;
            float inv  = __fdividef(1.f, Mp00 + r);
            k1 = Mp00 * inv; k2 = Mp01 * inv;
            m00 = Mp00 - k1 * Mp00;
            m01 = Mp01 - k1 * Mp01;
            m11 = Mp11 - k2 * Mp01;
        }
        s_c = __fdividef(k2, 1.f - k1);
        float A00 = 2.f * (1.f - k1), A01 = -(1.f - k1);
        float A10 = 1.f - 2.f * k2,   A11 = k2;
        float wa = k1, wb = k2;
        for (int j = 0; j < W; j++) {
            swa[j] = wa;
            float na = fmaf(A00, wa, A01 * wb);
            float nb = fmaf(A10, wa, A11 * wb);
            wa = na; wb = nb;
        }
    } else if (threadIdx.x >= 32) {
        // warps 1..5 stage the measurement tile (960 floats, 6 per thread)
        for (int i = (int)threadIdx.x - 32; i < NROWS * 6; i += NTH - 32) {
            int row = i / 6;
            int d   = i - row * 6;
            int gt  = base + row;
            sm[row * 7 + d] = (gt < T_LEN) ? meas[gt * 6 + d] : 0.f;
        }
    }
    __syncthreads();

    const int l  = threadIdx.x;
    const int tt = l / 6;
    const int d  = l - tt * 6;
    const float c = s_c;

    // a-values for times t0+tt*4-1 .. t0+tt*4+3  (A[0] is the k=-1 value)
    // highest time tH = t0+tt*4+3 -> shared row tt*4 + W + 3
    const float* mp = &sm[(tt * TPT + W + TPT - 1) * 7 + d];

    float A[TPT + 1];
    float w[TPT + 1];
#pragma unroll
    for (int j = 0; j <= TPT; j++) { A[j] = 0.f; w[j] = 0.f; }

#pragma unroll
    for (int s = 0; s < W + TPT; s++) {            // 36 iterations, fully unrolled
        w[0] = (s < W) ? swa[s] : 0.f;             // ramp/tail zeros fold at compile
        float x = mp[-s * 7];                      // m[tH - s]
#pragma unroll
        for (int k = 0; k <= TPT; k++)             // A[TPT-k] gets tap wa[s-k]
            A[TPT - k] = fmaf(w[k], x, A[TPT - k]);
#pragma unroll
        for (int k = TPT; k >= 1; k--) w[k] = w[k - 1];   // free renames
    }

    const int tb0 = t0 + tt * TPT;
#pragma unroll
    for (int k = 0; k < TPT; k++) {
        int t = tb0 + k;
        if (t < T_LEN) {
            float a  = A[k + 1];                    // a_t
            float ap = A[k];                        // a_{t-1}
            float mt = sm[(tt * TPT + W + k) * 7 + d];
            float cm = c * (mt - a);                // b_t = ap + cm
            est[t * 6 + d] = a;
            if (t + 1 < T_LEN)  pred[(t + 1) * 6 + d] = 2.f * a - ap - cm;
            if (t <= T_LEN - 2) vel [(t - 1) * 6 + d] = a - ap - cm;
        }
    }
}

// ---------------------------------------------------------------------------
extern "C" void kernel_launch(void* const* d_in, const int* in_sizes, int n_in,
                              void* d_out, int out_size) {
    const float* meas = (const float*)d_in[0];  // (T,6)
    const float* Q    = (const float*)d_in[1];  // (6,6)
    const float* R    = (const float*)d_in[2];  // (6,6)
    float* out = (float*)d_out;

    const int nb = 1 + (T_LEN - T_SEQ + TB - 1) / TB;   // 1 + 1024
    kf_kernel<<<nb, NTH>>>(meas, Q, R, out);
}

// round 7
// speedup vs baseline: 1.2060x; 1.2060x over previous
#include <cuda_runtime.h>

#define T_LEN 131072
#define W     32                 // FIR taps: rho^32 ~ 2e-7
#define T_SEQ 64                 // exact sequential prefix; (T_LEN-T_SEQ)%TB==0
#define TB    64                 // timesteps per FIR block
#define TPT   4                  // timesteps per thread
#define NTH   ((TB / TPT) * 6)   // 96 threads (3 warps)
#define N_RIC 14                 // Riccati fixed-point iterations
#define NROWS (TB + W)           // 96 shared rows

__global__ __launch_bounds__(NTH)
void kf_kernel(const float* __restrict__ meas,
               const float* __restrict__ Qm,
               const float* __restrict__ Rm,
               float* __restrict__ out) {
    float* est  = out;
    float* pred = out + (size_t)T_LEN * 6;
    float* vel  = out + (size_t)2 * T_LEN * 6;

    // ---------------- block 0: exact sequential transient ----------------
    if (blockIdx.x == 0) {
        const int d = threadIdx.x;
        if (d >= 6) return;
        const float q = Qm[0];
        const float r = Rm[0];
        float m00 = 1.f, m01 = 0.f, m11 = 1.f;   // cov_init = I12 -> M0 = I2
        float m0 = meas[d], m1 = meas[6 + d];
        est [d] = m0;  est [6 + d] = m1;
        pred[d] = m0;  pred[6 + d] = m1;
        vel [d] = m1 - m0;
        float a = m1, b = m0;
        for (int t = 2; t < T_SEQ; t++) {
            float Mp00 = 4.f * (m00 - m01) + m11 + q;
            float Mp01 = 2.f * m00 - m01;
            float Mp11 = m00;
            float inv  = __fdividef(1.f, Mp00 + r);
            float k1 = Mp00 * inv, k2 = Mp01 * inv;
            m00 = Mp00 - k1 * Mp00;
            m01 = Mp01 - k1 * Mp01;
            m11 = Mp11 - k2 * Mp01;
            float p  = 2.f * a - b;
            float e  = meas[t * 6 + d] - p;
            float an = fmaf(k1, e, p);
            float bn = fmaf(k2, e, a);
            est [t * 6 + d]       = an;
            pred[t * 6 + d]       = p;
            vel [(t - 1) * 6 + d] = an - bn;
            a = an; b = bn;
        }
        pred[T_SEQ * 6 + d] = 2.f * a - b;   // row T_SEQ: only writer
        return;
    }

    // ---------------- FIR blocks ----------------
    __shared__ float sm[NROWS * 7];   // stride 7: <=2-way bank conflicts

    const int t0   = T_SEQ + (blockIdx.x - 1) * TB;
    const int base = t0 - W;          // >= 32; base+NROWS-1 <= T_LEN-1 always

    // cooperative tile load: 576 floats, 6 per thread (in flight during Riccati)
#pragma unroll
    for (int k = 0; k < 6; k++) {
        int i   = threadIdx.x + k * NTH;
        int row = i / 6;
        int d   = i - row * 6;
        sm[row * 7 + d] = meas[(base + row) * 6 + d];
    }

    // per-thread (warp-uniform) Riccati fixed point — overlaps the LDGs above
    const float q = Qm[0], r = Rm[0];
    float m00 = 1.f, m01 = 0.f, m11 = 1.f;
    float k1 = 0.f, k2 = 0.f;
#pragma unroll
    for (int it = 0; it < N_RIC; it++) {
        float Mp00 = 4.f * (m00 - m01) + m11 + q;
        float Mp01 = 2.f * m00 - m01;
        float Mp11 = m00;
        float inv  = __fdividef(1.f, Mp00 + r);
        k1 = Mp00 * inv; k2 = Mp01 * inv;
        m00 = Mp00 - k1 * Mp00;
        m01 = Mp01 - k1 * Mp01;
        m11 = Mp11 - k2 * Mp01;
    }
    const float c   = __fdividef(k2, 1.f - k1);
    const float det = 1.f - k1;                   // det(A)
    const float tr  = 2.f * (1.f - k1) + k2;      // trace(A)

    __syncthreads();

    const int l  = threadIdx.x;
    const int tt = l / 6;
    const int d  = l - tt * 6;

    // x(s) = m[t0 + tt*TPT + (TPT-1) - s]; highest shared row tt*TPT + W + TPT-1
    const float* mp = &sm[(tt * TPT + W + TPT - 1) * 7 + d];

    float A[TPT + 1];
    float w[TPT + 1];
    float mt[TPT];
#pragma unroll
    for (int j = 0; j <= TPT; j++) { A[j] = 0.f; w[j] = 0.f; }

    // coefficient generator: wa_s, second-order recurrence (2 FMA/iter)
    float wa = k1;                                   // wa_0
    float wn = det * (2.f * k1 - k2);                // wa_1

#pragma unroll
    for (int s = 0; s < W + TPT; s++) {              // 36 iterations, fully unrolled
        w[0] = (s < W) ? wa : 0.f;                   // tail zeros fold at compile
        float x = mp[-s * 7];
        if (s < TPT) mt[TPT - 1 - s] = x;            // m[t] for b-reconstruction
#pragma unroll
        for (int k = 0; k <= TPT; k++)               // A[TPT-k] += wa_{s-k} * x
            A[TPT - k] = fmaf(w[k], x, A[TPT - k]);
#pragma unroll
        for (int k = TPT; k >= 1; k--) w[k] = w[k - 1];   // free renames
        if (s < W - 1) {                             // advance generator
            float nx = fmaf(tr, wn, -det * wa);
            wa = wn; wn = nx;
        }
    }

    const int tb0 = t0 + tt * TPT;
#pragma unroll
    for (int k = 0; k < TPT; k++) {
        int t = tb0 + k;                             // always < T_LEN (exact grid)
        float a  = A[k + 1];                         // a_t
        float ap = A[k];                             // a_{t-1}
        float cm = c * (mt[k] - a);                  // b_t = ap + cm
        est[t * 6 + d] = a;
        if (t + 1 < T_LEN)  pred[(t + 1) * 6 + d] = 2.f * a - ap - cm;
        if (t <= T_LEN - 2) vel [(t - 1) * 6 + d] = a - ap - cm;
    }
}

// ---------------------------------------------------------------------------
extern "C" void kernel_launch(void* const* d_in, const int* in_sizes, int n_in,
                              void* d_out, int out_size) {
    const float* meas = (const float*)d_in[0];  // (T,6)
    const float* Q    = (const float*)d_in[1];  // (6,6)
    const float* R    = (const float*)d_in[2];  // (6,6)
    float* out = (float*)d_out;

    const int nb = 1 + (T_LEN - T_SEQ) / TB;    // 1 + 2047
    kf_kernel<<<nb, NTH>>>(meas, Q, R, out);
}